// round 15
// baseline (speedup 1.0000x reference)
#include <cuda_runtime.h>
#include <cuda_fp16.h>

// ---------------------------------------------------------------------------
// MLPPredictor: score[e] = W3 @ relu(W2 @ relu(W1 @ [x[src];x[dst]] + b1) + b2) + b3
//
// W1 @ concat(xs,xd) = W1a@xs + W1b@xd -> node-level PQ GEMM (fp16 out),
// then per-edge gather + fused layer2 GEMM + layer3 dot.
//
// R14: edge work split across CTA PAIRS: blockIdx = 2*block + n_half.
// Each CTA (256 thr, 8 warps, warp 64x32) gathers the block's H1 and runs a
// single-pass MMA over its 128-wide N-half, then atomicAdds its partial
// w3-dot into out[] (pre-initialized to b3). 2 CTAs/SM -> cross-CTA overlap
// of gather / MMA / epilogue phases. fp16 m16n8k16, swizzled fragments.
// ---------------------------------------------------------------------------

#define D 256
#define NMAX 50000
#define AW 132                  // A frag block (16m x 16k = 128 words) + 4 pad
#define BW 66                   // B frag block (8n  x 16k =  64 words) + 2 pad
#define EA_WORDS (8 * 16 * AW)  // A buffer: 8 Mi x 16 Kk blocks = 16896 words
#define EBH_WORDS (16 * 2 * BW) // edge B chunk, N-half=128: 16 Ni x 2 Kk = 2112
#define BCH_WORDS (32 * 2 * BW) // node B chunk (256 n x 32 k) = 4224 words
#define NACH_WORDS (8 * 2 * AW) // node A chunk: 8 Mi x 2 Kk    = 2112 words

static __device__ __align__(16) __half g_PQh[(long long)NMAX * 512];  // 51.2 MB
static __device__ int   g_is64;
static __device__ __align__(16) __half g_W1h[256 * 512];
static __device__ __align__(16) __half g_W2h[256 * 256];

__device__ __forceinline__ unsigned f2h2(float lo, float hi) {
    __half2 h = __floats2half2_rn(lo, hi);
    return *reinterpret_cast<unsigned*>(&h);
}
__device__ __forceinline__ float2 h2f(unsigned u) {
    return __half22float2(*reinterpret_cast<__half2*>(&u));
}

__device__ __forceinline__ void mma16(float* d, const unsigned* a, const unsigned* b) {
    asm volatile(
        "mma.sync.aligned.m16n8k16.row.col.f32.f16.f16.f32 "
        "{%0,%1,%2,%3},{%4,%5,%6,%7},{%8,%9},{%0,%1,%2,%3};\n"
        : "+f"(d[0]), "+f"(d[1]), "+f"(d[2]), "+f"(d[3])
        : "r"(a[0]), "r"(a[1]), "r"(a[2]), "r"(a[3]), "r"(b[0]), "r"(b[1]));
}

// A-fragment reader: swizzled LDS.128 address (conflict-free; matches writers)
__device__ __forceinline__ unsigned a_rd_off(int lane) {
    return (unsigned)((lane * 4) ^ (((lane >> 3) & 3) << 2));
}

// ---------------------------------------------------------------------------
// prep: weight fp32->fp16 (blocks 0..191), idx dtype detect (192),
// out[] init to b3 (blocks 193+).
// ---------------------------------------------------------------------------
__global__ void prep(const float* __restrict__ W1, const float* __restrict__ W2,
                     const int* __restrict__ p, int E,
                     const float* __restrict__ b3, float* __restrict__ out) {
    if (blockIdx.x < 192) {
        int idx = blockIdx.x * blockDim.x + threadIdx.x;
        if (idx < 32768) {
            float4 v = ((const float4*)W1)[idx];
            ((__half2*)g_W1h)[idx * 2]     = __floats2half2_rn(v.x, v.y);
            ((__half2*)g_W1h)[idx * 2 + 1] = __floats2half2_rn(v.z, v.w);
        } else if (idx < 49152) {
            int j = idx - 32768;
            float4 v = ((const float4*)W2)[j];
            ((__half2*)g_W2h)[j * 2]     = __floats2half2_rn(v.x, v.y);
            ((__half2*)g_W2h)[j * 2 + 1] = __floats2half2_rn(v.z, v.w);
        }
    } else if (blockIdx.x == 192) {
        __shared__ int ok;
        if (threadIdx.x == 0) ok = 1;
        __syncthreads();
        int n = E < 1024 ? E : 1024;
        int bad = 0;
        for (int i = threadIdx.x; i < n; i += blockDim.x)
            if (p[2 * i + 1] != 0) bad = 1;
        if (bad) atomicAnd(&ok, 0);
        __syncthreads();
        if (threadIdx.x == 0) g_is64 = ok;
    } else {
        int idx = (blockIdx.x - 193) * blockDim.x + threadIdx.x;
        if (idx < E) out[idx] = b3[0];
    }
}

// ---------------------------------------------------------------------------
// Kernel 1: g_PQh[i, n0+c] = fp16( sum_k x[i,k] * W1[c, n0+k] )
// CTA 128x256, 16 warps, warp tile 64x32, K chunks of 32, double-buffered.
// (unchanged from R11 best)
// ---------------------------------------------------------------------------
__global__ __launch_bounds__(512) void node_gemm(const float* __restrict__ x,
                                                 int n_nodes) {
    extern __shared__ unsigned sm[];
    unsigned* Af = sm;                      // [2][NACH_WORDS]
    unsigned* Bf = sm + 2 * NACH_WORDS;     // [2][BCH_WORDS]

    const int tid = threadIdx.x, lane = tid & 31, warp = tid >> 5;
    const int wm = warp >> 3, wn = warp & 7;
    const int g = lane >> 2, tg = lane & 3;
    const int m0 = blockIdx.x * 128, n0 = blockIdx.y * 256;

    const int item = tid >> 1, sub = tid & 1;
    const int rA = item & 127, hA = item >> 7;
    const int gA = (rA & 15) & 7, rsA = (rA & 15) >> 3;
    const int swA = (gA >> 1) & 3;
    float4 rav[2]; uint4 rwv[2];

    auto LDA = [&](int kt) {
        int gr = m0 + rA; if (gr >= n_nodes) gr = n_nodes - 1;
        const float4* p = (const float4*)(x + (long long)gr * D + kt * 32 + hA * 16 + sub * 8);
        rav[0] = p[0]; rav[1] = p[1];
    };
    auto STA = [&](int buf) {
        unsigned* base = Af + buf * NACH_WORDS + ((rA >> 4) * 2 + hA) * AW + gA * 16 + rsA;
#pragma unroll
        for (int ii = 0; ii < 2; ii++) {
            int i = sub * 2 + ii;
            int t0 = (2 * i) & 3, t1 = (2 * i + 1) & 3, ch = i >> 1;
            base[((t0 ^ swA) << 2) + ch * 2] = f2h2(rav[ii].x, rav[ii].y);
            base[((t1 ^ swA) << 2) + ch * 2] = f2h2(rav[ii].z, rav[ii].w);
        }
    };
    const __half* Brow = g_W1h + (long long)(tid >> 1) * 512 + n0 + (tid & 1) * 16;
    auto LDW = [&](int kt) {
        const uint4* p = (const uint4*)(Brow + kt * 32);
        rwv[0] = p[0]; rwv[1] = p[1];
    };
    auto STW = [&](int buf) {
        const int row = tid >> 1, hB = tid & 1;
        const int Ni = row >> 3, gb = row & 7;
#pragma unroll
        for (int ii = 0; ii < 2; ii++) {
            int i = hB * 2 + ii;
            unsigned* q = Bf + buf * BCH_WORDS + (Ni * 2 + (i >> 1)) * BW + gb * 8 + (i & 1);
            q[0] = rwv[ii].x; q[2] = rwv[ii].y; q[4] = rwv[ii].z; q[6] = rwv[ii].w;
        }
    };

    float acc[4][4][4];
#pragma unroll
    for (int a = 0; a < 4; a++)
#pragma unroll
        for (int b = 0; b < 4; b++)
#pragma unroll
            for (int c = 0; c < 4; c++) acc[a][b][c] = 0.f;

    LDA(0); LDW(0); STA(0); STW(0);
    __syncthreads();

    const unsigned aoff = a_rd_off(lane);
    for (int kt = 0; kt < 8; ++kt) {
        const int cur = kt & 1;
        if (kt < 7) { LDA(kt + 1); LDW(kt + 1); }
        const unsigned* Ac = Af + cur * NACH_WORDS;
        const unsigned* Bc = Bf + cur * BCH_WORDS;
#pragma unroll
        for (int h = 0; h < 2; ++h) {
            uint4 af[4]; uint2 bf[4];
#pragma unroll
            for (int mi = 0; mi < 4; ++mi)
                af[mi] = *(const uint4*)(Ac + ((wm * 4 + mi) * 2 + h) * AW + aoff);
#pragma unroll
            for (int ni = 0; ni < 4; ++ni)
                bf[ni] = *(const uint2*)(Bc + ((wn * 4 + ni) * 2 + h) * BW + lane * 2);
#pragma unroll
            for (int mi = 0; mi < 4; ++mi)
#pragma unroll
                for (int ni = 0; ni < 4; ++ni)
                    mma16(acc[mi][ni], (const unsigned*)&af[mi], (const unsigned*)&bf[ni]);
        }
        if (kt < 7) { STA(cur ^ 1); STW(cur ^ 1); }
        __syncthreads();
    }

#pragma unroll
    for (int mi = 0; mi < 4; ++mi) {
        int r0 = m0 + wm * 64 + mi * 16 + g;
        int r1 = r0 + 8;
#pragma unroll
        for (int ni = 0; ni < 4; ++ni) {
            int c = n0 + wn * 32 + ni * 8 + tg * 2;
            if (r0 < n_nodes)
                *(unsigned*)(g_PQh + (long long)r0 * 512 + c) = f2h2(acc[mi][ni][0], acc[mi][ni][1]);
            if (r1 < n_nodes)
                *(unsigned*)(g_PQh + (long long)r1 * 512 + c) = f2h2(acc[mi][ni][2], acc[mi][ni][3]);
        }
    }
}

// ---------------------------------------------------------------------------
// Kernel 3: blockIdx = 2*block + n_half. 256 threads, 8 warps, warp 64x32.
// Full gather of the block's H1, single-pass MMA over this CTA's 128-wide
// N-half, partial w3-dot atomicAdded into out[] (pre-init to b3).
// 2 CTAs/SM -> cross-CTA phase overlap.
// ---------------------------------------------------------------------------
__global__ __launch_bounds__(256, 2) void edge_mlp(const void* __restrict__ srcv,
                                                   const void* __restrict__ dstv,
                                                   const float* __restrict__ b1,
                                                   const float* __restrict__ b2,
                                                   const float* __restrict__ W3,
                                                   float* __restrict__ out, int E) {
    extern __shared__ unsigned sm[];
    unsigned* Af = sm;                        // [EA_WORDS]
    unsigned* Bf = sm + EA_WORDS;             // [2][EBH_WORDS]
    float* b1s   = (float*)(Bf + 2 * EBH_WORDS);  // 256
    float* b2s   = b1s + 256;                     // 128 (this n-half)
    float* w3s   = b2s + 128;                     // 128
    float* score = w3s + 128;                     // 128

    const int tid = threadIdx.x, lane = tid & 31, warp = tid >> 5;
    const int wm = warp >> 2, wn = warp & 3;
    const int g = lane >> 2, tg = lane & 3;
    const int nc = blockIdx.x & 1;            // which N-half
    const int e0 = (blockIdx.x >> 1) * 128;   // edge block base
    const int is64 = g_is64;

    b1s[tid] = b1[tid];
    if (tid < 128) {
        b2s[tid] = b2[nc * 128 + tid];
        w3s[tid] = W3[nc * 128 + tid];
        score[tid] = 0.f;
    }
    __syncthreads();   // b1s needed by gather

    // ---- W2 half-chunk stream: 128 rows x 32 halves, thread -> (row, hB) ----
    uint4 rwv[2];
    const int rowB = tid >> 1, hB = tid & 1;
    const int NiB = rowB >> 3, gB = rowB & 7;
    const __half* Brow = g_W2h + (long long)(nc * 128 + rowB) * 256 + hB * 16;
    auto LDW = [&](int kt) {
        const uint4* p = (const uint4*)(Brow + kt * 32);
        rwv[0] = p[0]; rwv[1] = p[1];
    };
    auto STW = [&](int buf) {
#pragma unroll
        for (int ii = 0; ii < 2; ii++) {
            int i = hB * 2 + ii;
            unsigned* q = Bf + buf * EBH_WORDS + (NiB * 2 + (i >> 1)) * BW + gB * 8 + (i & 1);
            q[0] = rwv[ii].x; q[2] = rwv[ii].y; q[4] = rwv[ii].z; q[6] = rwv[ii].w;
        }
    };

    LDW(0);  // overlap W2 chunk-0 loads with the gather

    // ---- gather + layer 1: row r = tid>>1, column half l2 = tid&1 ----
    {
        const int r = tid >> 1, l2 = tid & 1;
        const int Mi = r >> 4, gg = (r & 15) & 7, hi = (r & 15) >> 3;
        const int swz = (gg >> 1) & 3;
        unsigned* fragp = Af + Mi * 16 * AW + gg * 16 + hi;
        int e = e0 + r;
        if (e >= E) e = 0;   // garbage rows computed, never stored
        long long s, d;
        if (is64) { s = ((const long long*)srcv)[e]; d = ((const long long*)dstv)[e]; }
        else      { s = ((const int*)srcv)[e];       d = ((const int*)dstv)[e]; }
        const uint4* P8 = (const uint4*)(g_PQh + s * 512);
        const uint4* Q8 = (const uint4*)(g_PQh + d * 512 + 256);
#pragma unroll
        for (int i = 0; i < 16; i++) {
            int c8 = i * 2 + l2;           // uint4 (8-half) index, 0..31
            uint4 pu = P8[c8], qu = Q8[c8];
            const float* bb = b1s + c8 * 8;
            float v[8];
            float2 a, b;
            a = h2f(pu.x); b = h2f(qu.x);
            v[0] = fmaxf(a.x + b.x + bb[0], 0.f); v[1] = fmaxf(a.y + b.y + bb[1], 0.f);
            a = h2f(pu.y); b = h2f(qu.y);
            v[2] = fmaxf(a.x + b.x + bb[2], 0.f); v[3] = fmaxf(a.y + b.y + bb[3], 0.f);
            a = h2f(pu.z); b = h2f(qu.z);
            v[4] = fmaxf(a.x + b.x + bb[4], 0.f); v[5] = fmaxf(a.y + b.y + bb[5], 0.f);
            a = h2f(pu.w); b = h2f(qu.w);
            v[6] = fmaxf(a.x + b.x + bb[6], 0.f); v[7] = fmaxf(a.y + b.y + bb[7], 0.f);
            const int Kk = c8 >> 1, hc = (c8 & 1) * 2;
            unsigned* basep = fragp + Kk * AW;
#pragma unroll
            for (int t = 0; t < 4; t++)
                basep[((t ^ swz) << 2) + hc] = f2h2(v[2 * t], v[2 * t + 1]);
        }
    }
    STW(0);
    __syncthreads();

    float acc[4][4][4];
#pragma unroll
    for (int a = 0; a < 4; a++)
#pragma unroll
        for (int b = 0; b < 4; b++)
#pragma unroll
            for (int c = 0; c < 4; c++) acc[a][b][c] = 0.f;

    const unsigned aoff = a_rd_off(lane);
    const unsigned* Awarp = Af + (wm * 4) * 16 * AW + aoff;
    for (int kt = 0; kt < 8; ++kt) {
        const int cur = kt & 1;
        if (kt < 7) LDW(kt + 1);
        const unsigned* Bc = Bf + cur * EBH_WORDS;
#pragma unroll
        for (int h = 0; h < 2; ++h) {
            const int Kkg = kt * 2 + h;
            uint4 af[4]; uint2 bf[4];
#pragma unroll
            for (int mi = 0; mi < 4; ++mi)
                af[mi] = *(const uint4*)(Awarp + (mi * 16 + Kkg) * AW);
#pragma unroll
            for (int ni = 0; ni < 4; ++ni)
                bf[ni] = *(const uint2*)(Bc + ((wn * 4 + ni) * 2 + h) * BW + lane * 2);
#pragma unroll
            for (int mi = 0; mi < 4; ++mi)
#pragma unroll
                for (int ni = 0; ni < 4; ++ni)
                    mma16(acc[mi][ni], (const unsigned*)&af[mi], (const unsigned*)&bf[ni]);
        }
        if (kt < 7) STW(cur ^ 1);
        __syncthreads();
    }

    // ---- fused layer-2 bias/relu + layer-3 partial dot (this n-half) ----
#pragma unroll
    for (int mi = 0; mi < 4; ++mi) {
        float rs0 = 0.f, rs1 = 0.f;
#pragma unroll
        for (int ni = 0; ni < 4; ++ni) {
            int n = wn * 32 + ni * 8 + tg * 2;   // local n within the half
            float w0 = w3s[n], w1 = w3s[n + 1];
            float c0 = b2s[n], c1 = b2s[n + 1];
            rs0 += fmaxf(acc[mi][ni][0] + c0, 0.f) * w0 + fmaxf(acc[mi][ni][1] + c1, 0.f) * w1;
            rs1 += fmaxf(acc[mi][ni][2] + c0, 0.f) * w0 + fmaxf(acc[mi][ni][3] + c1, 0.f) * w1;
        }
        rs0 += __shfl_xor_sync(0xffffffffu, rs0, 1);
        rs0 += __shfl_xor_sync(0xffffffffu, rs0, 2);
        rs1 += __shfl_xor_sync(0xffffffffu, rs1, 1);
        rs1 += __shfl_xor_sync(0xffffffffu, rs1, 2);
        if (tg == 0) {
            atomicAdd(&score[wm * 64 + mi * 16 + g], rs0);
            atomicAdd(&score[wm * 64 + mi * 16 + g + 8], rs1);
        }
    }
    __syncthreads();

    if (tid < 128) {
        int e = e0 + tid;
        if (e < E) atomicAdd(out + e, score[tid]);
    }
}

// ---------------------------------------------------------------------------
// Launch
// ---------------------------------------------------------------------------
extern "C" void kernel_launch(void* const* d_in, const int* in_sizes, int n_in,
                              void* d_out, int out_size) {
    const float* x  = (const float*)d_in[0];
    const void*  sv = d_in[1];
    const void*  dv = d_in[2];
    const float* W1 = (const float*)d_in[3];
    const float* b1 = (const float*)d_in[4];
    const float* W2 = (const float*)d_in[5];
    const float* b2 = (const float*)d_in[6];
    const float* W3 = (const float*)d_in[7];
    const float* b3 = (const float*)d_in[8];
    float* out = (float*)d_out;

    const int n_nodes = in_sizes[0] / D;
    const int E       = in_sizes[1];
    const int NB      = (E + 127) / 128;

    const int SM_NODE = (2 * NACH_WORDS + 2 * BCH_WORDS) * 4;          // 50688 B
    const int SM_EDGE = (EA_WORDS + 2 * EBH_WORDS + 640) * 4;          // 87040 B
    cudaFuncSetAttribute(node_gemm, cudaFuncAttributeMaxDynamicSharedMemorySize, SM_NODE);
    cudaFuncSetAttribute(edge_mlp,  cudaFuncAttributeMaxDynamicSharedMemorySize, SM_EDGE);

    prep<<<193 + (E + 255) / 256, 256>>>(W1, W2, (const int*)sv, E, b3, out);

    dim3 g1((n_nodes + 127) / 128, 2);
    node_gemm<<<g1, 512, SM_NODE>>>(x, n_nodes);

    edge_mlp<<<2 * NB, 256, SM_EDGE>>>(sv, dv, b1, b2, W3, out, E);
}

// round 16
// speedup vs baseline: 1.2697x; 1.2697x over previous
#include <cuda_runtime.h>
#include <cuda_fp16.h>

// ---------------------------------------------------------------------------
// MLPPredictor: score[e] = W3 @ relu(W2 @ relu(W1 @ [x[src];x[dst]] + b1) + b2) + b3
//
// W1 @ concat(xs,xd) = W1a@xs + W1b@xd -> node-level PQ GEMM (fp16 out),
// then per-edge gather + fused layer2 GEMM + layer3 dot.
//
// R15: weights pre-permuted into MMA-fragment order in gmem; B loaded with
// cp.async (LDGSTS) into a fully-resident 128KB smem image, committed as 8
// groups with progressive wait_group(7-kt) -> MMA on chunk 0 overlaps the
// remaining copies AND the gather. No B register staging, no B STS.
// ---------------------------------------------------------------------------

#define D 256
#define NMAX 50000
#define AW 132                  // A frag block (16m x 16k = 128 words) + 4 pad
#define EA_WORDS (8 * 16 * AW)  // A buffer: 8 Mi x 16 Kk blocks = 16896 words
#define BCH 4096                // B chunk: 64 blocks x 64 words = 16KB (no pad)

static __device__ __align__(16) __half g_PQh[(long long)NMAX * 512];  // 51.2 MB
static __device__ int   g_is64;
static __device__ __align__(16) unsigned g_W1f[2 * 8 * BCH];  // fragment-ordered W1
static __device__ __align__(16) unsigned g_W2f[8 * BCH];      // fragment-ordered W2

__device__ __forceinline__ unsigned f2h2(float lo, float hi) {
    __half2 h = __floats2half2_rn(lo, hi);
    return *reinterpret_cast<unsigned*>(&h);
}
__device__ __forceinline__ float2 h2f(unsigned u) {
    return __half22float2(*reinterpret_cast<__half2*>(&u));
}

__device__ __forceinline__ void mma16(float* d, const unsigned* a, const unsigned* b) {
    asm volatile(
        "mma.sync.aligned.m16n8k16.row.col.f32.f16.f16.f32 "
        "{%0,%1,%2,%3},{%4,%5,%6,%7},{%8,%9},{%0,%1,%2,%3};\n"
        : "+f"(d[0]), "+f"(d[1]), "+f"(d[2]), "+f"(d[3])
        : "r"(a[0]), "r"(a[1]), "r"(a[2]), "r"(a[3]), "r"(b[0]), "r"(b[1]));
}

__device__ __forceinline__ unsigned a_rd_off(int lane) {
    return (unsigned)((lane * 4) ^ (((lane >> 3) & 3) << 2));
}

// ---- cp.async helpers ----
__device__ __forceinline__ void cp16(unsigned dst, const void* src) {
    asm volatile("cp.async.cg.shared.global [%0], [%1], 16;" :: "r"(dst), "l"(src));
}
__device__ __forceinline__ void cpcommit() {
    asm volatile("cp.async.commit_group;" ::: "memory");
}
__device__ __forceinline__ void cpwait(int n) {
    switch (n) {
        case 0: asm volatile("cp.async.wait_group 0;" ::: "memory"); break;
        case 1: asm volatile("cp.async.wait_group 1;" ::: "memory"); break;
        case 2: asm volatile("cp.async.wait_group 2;" ::: "memory"); break;
        case 3: asm volatile("cp.async.wait_group 3;" ::: "memory"); break;
        case 4: asm volatile("cp.async.wait_group 4;" ::: "memory"); break;
        case 5: asm volatile("cp.async.wait_group 5;" ::: "memory"); break;
        case 6: asm volatile("cp.async.wait_group 6;" ::: "memory"); break;
        default: asm volatile("cp.async.wait_group 7;" ::: "memory"); break;
    }
}

// ---------------------------------------------------------------------------
// prep: permute W1/W2 (fp32, row-major) into fragment-ordered fp16 images.
// Fragment word within a chunk: (Ni*2+h)*64 + g*8 + tg*2 + reg
//   n = Ni*8+g ; k = ck*32 + h*16 + reg*8 + tg*2  (value = half2(k, k+1)).
// blocks [0,128): W2 (32768 half2) ; [128,384): W1 (65536) ; 384: idx detect.
// ---------------------------------------------------------------------------
__global__ void prep(const float* __restrict__ W1, const float* __restrict__ W2,
                     const int* __restrict__ p, int E) {
    if (blockIdx.x < 128) {
        int idx = blockIdx.x * 256 + threadIdx.x;          // 0..32767
        int reg = idx & 1, tg = (idx >> 1) & 3, g = (idx >> 3) & 7;
        int h = (idx >> 6) & 1, Ni = (idx >> 7) & 31, ck = idx >> 12;
        int n = Ni * 8 + g;
        int k = ck * 32 + h * 16 + reg * 8 + tg * 2;
        float2 v = *(const float2*)(W2 + n * 256 + k);
        g_W2f[ck * BCH + (Ni * 2 + h) * 64 + g * 8 + tg * 2 + reg] = f2h2(v.x, v.y);
    } else if (blockIdx.x < 384) {
        int idx = (blockIdx.x - 128) * 256 + threadIdx.x;  // 0..65535
        int half = idx >> 15, rem = idx & 32767;
        int reg = rem & 1, tg = (rem >> 1) & 3, g = (rem >> 3) & 7;
        int h = (rem >> 6) & 1, Ni = (rem >> 7) & 31, ck = rem >> 12;
        int n = Ni * 8 + g;
        int k = half * 256 + ck * 32 + h * 16 + reg * 8 + tg * 2;
        float2 v = *(const float2*)(W1 + n * 512 + k);
        g_W1f[half * 8 * BCH + ck * BCH + (Ni * 2 + h) * 64 + g * 8 + tg * 2 + reg] = f2h2(v.x, v.y);
    } else {
        __shared__ int ok;
        if (threadIdx.x == 0) ok = 1;
        __syncthreads();
        int n = E < 1024 ? E : 1024;
        int bad = 0;
        for (int i = threadIdx.x; i < n; i += blockDim.x)
            if (p[2 * i + 1] != 0) bad = 1;
        if (bad) atomicAnd(&ok, 0);
        __syncthreads();
        if (threadIdx.x == 0) g_is64 = ok;
    }
}

// ---------------------------------------------------------------------------
// Kernel 1: g_PQh[i, n0+c] = fp16( sum_k x[i,k] * W1[c, n0+k] )
// CTA 128x256, 16 warps, warp 64x32. Full A (convert+STS) + full B (cp.async,
// 8 groups), progressive wait, per-kt barrier only for visibility.
// ---------------------------------------------------------------------------
__global__ __launch_bounds__(512) void node_gemm(const float* __restrict__ x,
                                                 int n_nodes) {
    extern __shared__ unsigned sm[];
    unsigned* Af = sm;               // [EA_WORDS]
    unsigned* Bf = sm + EA_WORDS;    // [8][BCH]

    const int tid = threadIdx.x, lane = tid & 31, warp = tid >> 5;
    const int wm = warp >> 3, wn = warp & 7;
    const int g = lane >> 2, tg = lane & 3;
    const int m0 = blockIdx.x * 128, half = blockIdx.y;

    // ---- issue all B copies (8 groups) before touching A ----
    {
        unsigned bb = (unsigned)__cvta_generic_to_shared(Bf) + tid * 32;
        const unsigned* src = g_W1f + half * 8 * BCH + tid * 8;
#pragma unroll
        for (int ck = 0; ck < 8; ck++) {
            cp16(bb + ck * 16384, src + ck * BCH);
            cp16(bb + ck * 16384 + 16, src + ck * BCH + 4);
            cpcommit();
        }
    }

    // ---- full A load into fragment layout (swizzled) ----
    {
        const int r = tid >> 2, l4 = tid & 3;
        const int Mi = r >> 4, gg = (r & 15) & 7, hi = (r & 15) >> 3;
        const int swz = (gg >> 1) & 3;
        unsigned* fragp = Af + Mi * 16 * AW + gg * 16 + hi;
        int gr = m0 + r; if (gr >= n_nodes) gr = n_nodes - 1;
        const float4* X4 = (const float4*)(x + (long long)gr * D);
#pragma unroll
        for (int i = 0; i < 8; i++) {
            int c8 = i * 4 + l4;           // 8-float group index, 0..31
            float4 a0 = X4[c8 * 2], a1 = X4[c8 * 2 + 1];
            const int Kk = c8 >> 1, hc = (c8 & 1) * 2;
            unsigned* basep = fragp + Kk * AW;
            basep[((0 ^ swz) << 2) + hc] = f2h2(a0.x, a0.y);
            basep[((1 ^ swz) << 2) + hc] = f2h2(a0.z, a0.w);
            basep[((2 ^ swz) << 2) + hc] = f2h2(a1.x, a1.y);
            basep[((3 ^ swz) << 2) + hc] = f2h2(a1.z, a1.w);
        }
    }
    __syncthreads();   // A visible to all warps

    float acc[4][4][4];
#pragma unroll
    for (int a = 0; a < 4; a++)
#pragma unroll
        for (int b = 0; b < 4; b++)
#pragma unroll
            for (int c = 0; c < 4; c++) acc[a][b][c] = 0.f;

    const unsigned aoff = a_rd_off(lane);
    const unsigned* Awarp = Af + (wm * 4) * 16 * AW + aoff;
    for (int kt = 0; kt < 8; ++kt) {
        cpwait(7 - kt);
        __syncthreads();               // chunk kt visible to all threads
        const unsigned* Bc = Bf + kt * BCH;
#pragma unroll
        for (int h = 0; h < 2; ++h) {
            const int Kkg = kt * 2 + h;
            uint4 af[4]; uint2 bf[4];
#pragma unroll
            for (int mi = 0; mi < 4; ++mi)
                af[mi] = *(const uint4*)(Awarp + (mi * 16 + Kkg) * AW);
#pragma unroll
            for (int ni = 0; ni < 4; ++ni)
                bf[ni] = *(const uint2*)(Bc + ((wn * 4 + ni) * 2 + h) * 64 + lane * 2);
#pragma unroll
            for (int mi = 0; mi < 4; ++mi)
#pragma unroll
                for (int ni = 0; ni < 4; ++ni)
                    mma16(acc[mi][ni], (const unsigned*)&af[mi], (const unsigned*)&bf[ni]);
        }
    }

#pragma unroll
    for (int mi = 0; mi < 4; ++mi) {
        int r0 = m0 + wm * 64 + mi * 16 + g;
        int r1 = r0 + 8;
#pragma unroll
        for (int ni = 0; ni < 4; ++ni) {
            int c = half * 256 + wn * 32 + ni * 8 + tg * 2;
            if (r0 < n_nodes)
                *(unsigned*)(g_PQh + (long long)r0 * 512 + c) = f2h2(acc[mi][ni][0], acc[mi][ni][1]);
            if (r1 < n_nodes)
                *(unsigned*)(g_PQh + (long long)r1 * 512 + c) = f2h2(acc[mi][ni][2], acc[mi][ni][3]);
        }
    }
}

// ---------------------------------------------------------------------------
// Kernel 3: 128 edges/CTA, 512 threads, 16 warps, warp 64x32, one N pass.
// B via cp.async (8 groups, progressive wait); gather overlaps the copies.
// ---------------------------------------------------------------------------
__global__ __launch_bounds__(512) void edge_mlp(const void* __restrict__ srcv,
                                                const void* __restrict__ dstv,
                                                const float* __restrict__ b1,
                                                const float* __restrict__ b2,
                                                const float* __restrict__ W3,
                                                const float* __restrict__ b3,
                                                float* __restrict__ out, int E) {
    extern __shared__ unsigned sm[];
    unsigned* Af = sm;                      // [EA_WORDS]
    unsigned* Bf = sm + EA_WORDS;           // [8][BCH]
    float* b2s   = (float*)(Bf + 8 * BCH);  // 256
    float* w3s   = b2s + 256;               // 256
    float* b1s   = w3s + 256;               // 256
    float* score = b1s + 256;               // 128

    const int tid = threadIdx.x, lane = tid & 31, warp = tid >> 5;
    const int wm = warp >> 3, wn = warp & 7;
    const int g = lane >> 2, tg = lane & 3;
    const int e0 = blockIdx.x * 128;
    const int is64 = g_is64;

    // ---- issue all B copies (8 groups) first: they land during the gather ----
    {
        unsigned bb = (unsigned)__cvta_generic_to_shared(Bf) + tid * 32;
        const unsigned* src = g_W2f + tid * 8;
#pragma unroll
        for (int ck = 0; ck < 8; ck++) {
            cp16(bb + ck * 16384, src + ck * BCH);
            cp16(bb + ck * 16384 + 16, src + ck * BCH + 4);
            cpcommit();
        }
    }

    if (tid < 256) {
        b2s[tid] = b2[tid];
        w3s[tid] = W3[tid];
        b1s[tid] = b1[tid];
    }
    if (tid < 128) score[tid] = b3[0];
    __syncthreads();   // b1s needed by the gather

    // ---- gather + layer 1 (fp16 PQ, coalesced uint4, swizzled frag store) ----
    {
        const int r = tid >> 2, l4 = tid & 3;
        const int Mi = r >> 4, gg = (r & 15) & 7, hi = (r & 15) >> 3;
        const int swz = (gg >> 1) & 3;
        unsigned* fragp = Af + Mi * 16 * AW + gg * 16 + hi;
        int e = e0 + r;
        if (e >= E) e = 0;   // garbage rows computed, never stored
        long long s, d;
        if (is64) { s = ((const long long*)srcv)[e]; d = ((const long long*)dstv)[e]; }
        else      { s = ((const int*)srcv)[e];       d = ((const int*)dstv)[e]; }
        const uint4* P8 = (const uint4*)(g_PQh + s * 512);
        const uint4* Q8 = (const uint4*)(g_PQh + d * 512 + 256);
#pragma unroll
        for (int i = 0; i < 8; i++) {
            int c8 = i * 4 + l4;           // uint4 (8-half) index, 0..31
            uint4 pu = P8[c8], qu = Q8[c8];
            const float* bb = b1s + c8 * 8;
            float v[8];
            float2 a, b;
            a = h2f(pu.x); b = h2f(qu.x);
            v[0] = fmaxf(a.x + b.x + bb[0], 0.f); v[1] = fmaxf(a.y + b.y + bb[1], 0.f);
            a = h2f(pu.y); b = h2f(qu.y);
            v[2] = fmaxf(a.x + b.x + bb[2], 0.f); v[3] = fmaxf(a.y + b.y + bb[3], 0.f);
            a = h2f(pu.z); b = h2f(qu.z);
            v[4] = fmaxf(a.x + b.x + bb[4], 0.f); v[5] = fmaxf(a.y + b.y + bb[5], 0.f);
            a = h2f(pu.w); b = h2f(qu.w);
            v[6] = fmaxf(a.x + b.x + bb[6], 0.f); v[7] = fmaxf(a.y + b.y + bb[7], 0.f);
            const int Kk = c8 >> 1, hc = (c8 & 1) * 2;
            unsigned* basep = fragp + Kk * AW;
#pragma unroll
            for (int t = 0; t < 4; t++)
                basep[((t ^ swz) << 2) + hc] = f2h2(v[2 * t], v[2 * t + 1]);
        }
    }
    __syncthreads();   // A visible

    float acc[4][4][4];
#pragma unroll
    for (int a = 0; a < 4; a++)
#pragma unroll
        for (int b = 0; b < 4; b++)
#pragma unroll
            for (int c = 0; c < 4; c++) acc[a][b][c] = 0.f;

    const unsigned aoff = a_rd_off(lane);
    const unsigned* Awarp = Af + (wm * 4) * 16 * AW + aoff;
    for (int kt = 0; kt < 8; ++kt) {
        cpwait(7 - kt);
        __syncthreads();               // chunk kt visible to all threads
        const unsigned* Bc = Bf + kt * BCH;
#pragma unroll
        for (int h = 0; h < 2; ++h) {
            const int Kkg = kt * 2 + h;
            uint4 af[4]; uint2 bf[4];
#pragma unroll
            for (int mi = 0; mi < 4; ++mi)
                af[mi] = *(const uint4*)(Awarp + (mi * 16 + Kkg) * AW);
#pragma unroll
            for (int ni = 0; ni < 4; ++ni)
                bf[ni] = *(const uint2*)(Bc + ((wn * 4 + ni) * 2 + h) * 64 + lane * 2);
#pragma unroll
            for (int mi = 0; mi < 4; ++mi)
#pragma unroll
                for (int ni = 0; ni < 4; ++ni)
                    mma16(acc[mi][ni], (const unsigned*)&af[mi], (const unsigned*)&bf[ni]);
        }
    }

    // ---- fused layer-2 bias/relu + layer-3 dot reduction ----
#pragma unroll
    for (int mi = 0; mi < 4; ++mi) {
        float rs0 = 0.f, rs1 = 0.f;
#pragma unroll
        for (int ni = 0; ni < 4; ++ni) {
            int n = wn * 32 + ni * 8 + tg * 2;
            float w0 = w3s[n], w1 = w3s[n + 1];
            float c0 = b2s[n], c1 = b2s[n + 1];
            rs0 += fmaxf(acc[mi][ni][0] + c0, 0.f) * w0 + fmaxf(acc[mi][ni][1] + c1, 0.f) * w1;
            rs1 += fmaxf(acc[mi][ni][2] + c0, 0.f) * w0 + fmaxf(acc[mi][ni][3] + c1, 0.f) * w1;
        }
        rs0 += __shfl_xor_sync(0xffffffffu, rs0, 1);
        rs0 += __shfl_xor_sync(0xffffffffu, rs0, 2);
        rs1 += __shfl_xor_sync(0xffffffffu, rs1, 1);
        rs1 += __shfl_xor_sync(0xffffffffu, rs1, 2);
        if (tg == 0) {
            atomicAdd(&score[wm * 64 + mi * 16 + g], rs0);
            atomicAdd(&score[wm * 64 + mi * 16 + g + 8], rs1);
        }
    }
    __syncthreads();

    if (tid < 128) {
        int e = e0 + tid;
        if (e < E) out[e] = score[tid];
    }
}

// ---------------------------------------------------------------------------
// Launch
// ---------------------------------------------------------------------------
extern "C" void kernel_launch(void* const* d_in, const int* in_sizes, int n_in,
                              void* d_out, int out_size) {
    const float* x  = (const float*)d_in[0];
    const void*  sv = d_in[1];
    const void*  dv = d_in[2];
    const float* W1 = (const float*)d_in[3];
    const float* b1 = (const float*)d_in[4];
    const float* W2 = (const float*)d_in[5];
    const float* b2 = (const float*)d_in[6];
    const float* W3 = (const float*)d_in[7];
    const float* b3 = (const float*)d_in[8];
    float* out = (float*)d_out;

    const int n_nodes = in_sizes[0] / D;
    const int E       = in_sizes[1];

    const int SM_NODE = (EA_WORDS + 8 * BCH) * 4;          // 198656 B
    const int SM_EDGE = (EA_WORDS + 8 * BCH + 896) * 4;    // 202240 B
    cudaFuncSetAttribute(node_gemm, cudaFuncAttributeMaxDynamicSharedMemorySize, SM_NODE);
    cudaFuncSetAttribute(edge_mlp,  cudaFuncAttributeMaxDynamicSharedMemorySize, SM_EDGE);

    prep<<<385, 256>>>(W1, W2, (const int*)sv, E);

    dim3 g1((n_nodes + 127) / 128, 2);
    node_gemm<<<g1, 512, SM_NODE>>>(x, n_nodes);

    int g2 = (E + 127) / 128;
    edge_mlp<<<g2, 512, SM_EDGE>>>(sv, dv, b1, b2, W3, b3, out, E);
}

// round 17
// speedup vs baseline: 1.3583x; 1.0697x over previous
#include <cuda_runtime.h>
#include <cuda_fp16.h>

// ---------------------------------------------------------------------------
// MLPPredictor: score[e] = W3 @ relu(W2 @ relu(W1 @ [x[src];x[dst]] + b1) + b2) + b3
//
// W1 @ concat(xs,xd) = W1a@xs + W1b@xd -> node-level PQ GEMM (fp16 out),
// then per-edge gather + fused layer2 GEMM + layer3 dot.
//
// R16 = R15 (fragment-ordered weights + cp.async B, 512 thr, warp 64x32) +
//   - edge CTA processes TWO 128-edge M-halves against ONE resident W2 image
//     (W2 DMA halved, waves halved; half 1 mainloop wait/barrier-free)
//   - gather remapped to 8 threads/row: 128B-contiguous LDG -> wavefronts halved
// ---------------------------------------------------------------------------

#define D 256
#define NMAX 50000
#define AW 132                  // A frag block (16m x 16k = 128 words) + 4 pad
#define EA_WORDS (8 * 16 * AW)  // A buffer: 8 Mi x 16 Kk blocks = 16896 words
#define BCH 4096                // B chunk: 64 blocks x 64 words = 16KB (no pad)

static __device__ __align__(16) __half g_PQh[(long long)NMAX * 512];  // 51.2 MB
static __device__ int   g_is64;
static __device__ __align__(16) unsigned g_W1f[2 * 8 * BCH];  // fragment-ordered W1
static __device__ __align__(16) unsigned g_W2f[8 * BCH];      // fragment-ordered W2

__device__ __forceinline__ unsigned f2h2(float lo, float hi) {
    __half2 h = __floats2half2_rn(lo, hi);
    return *reinterpret_cast<unsigned*>(&h);
}
__device__ __forceinline__ float2 h2f(unsigned u) {
    return __half22float2(*reinterpret_cast<__half2*>(&u));
}

__device__ __forceinline__ void mma16(float* d, const unsigned* a, const unsigned* b) {
    asm volatile(
        "mma.sync.aligned.m16n8k16.row.col.f32.f16.f16.f32 "
        "{%0,%1,%2,%3},{%4,%5,%6,%7},{%8,%9},{%0,%1,%2,%3};\n"
        : "+f"(d[0]), "+f"(d[1]), "+f"(d[2]), "+f"(d[3])
        : "r"(a[0]), "r"(a[1]), "r"(a[2]), "r"(a[3]), "r"(b[0]), "r"(b[1]));
}

__device__ __forceinline__ unsigned a_rd_off(int lane) {
    return (unsigned)((lane * 4) ^ (((lane >> 3) & 3) << 2));
}

// ---- cp.async helpers ----
__device__ __forceinline__ void cp16(unsigned dst, const void* src) {
    asm volatile("cp.async.cg.shared.global [%0], [%1], 16;" :: "r"(dst), "l"(src));
}
__device__ __forceinline__ void cpcommit() {
    asm volatile("cp.async.commit_group;" ::: "memory");
}
__device__ __forceinline__ void cpwait(int n) {
    switch (n) {
        case 0: asm volatile("cp.async.wait_group 0;" ::: "memory"); break;
        case 1: asm volatile("cp.async.wait_group 1;" ::: "memory"); break;
        case 2: asm volatile("cp.async.wait_group 2;" ::: "memory"); break;
        case 3: asm volatile("cp.async.wait_group 3;" ::: "memory"); break;
        case 4: asm volatile("cp.async.wait_group 4;" ::: "memory"); break;
        case 5: asm volatile("cp.async.wait_group 5;" ::: "memory"); break;
        case 6: asm volatile("cp.async.wait_group 6;" ::: "memory"); break;
        default: asm volatile("cp.async.wait_group 7;" ::: "memory"); break;
    }
}

// ---------------------------------------------------------------------------
// prep: permute W1/W2 (fp32, row-major) into fragment-ordered fp16 images.
// Fragment word within a chunk: (Ni*2+h)*64 + g*8 + tg*2 + reg
//   n = Ni*8+g ; k = ck*32 + h*16 + reg*8 + tg*2  (value = half2(k, k+1)).
// blocks [0,128): W2 ; [128,384): W1 ; 384: idx dtype detect.
// ---------------------------------------------------------------------------
__global__ void prep(const float* __restrict__ W1, const float* __restrict__ W2,
                     const int* __restrict__ p, int E) {
    if (blockIdx.x < 128) {
        int idx = blockIdx.x * 256 + threadIdx.x;          // 0..32767
        int reg = idx & 1, tg = (idx >> 1) & 3, g = (idx >> 3) & 7;
        int h = (idx >> 6) & 1, Ni = (idx >> 7) & 31, ck = idx >> 12;
        int n = Ni * 8 + g;
        int k = ck * 32 + h * 16 + reg * 8 + tg * 2;
        float2 v = *(const float2*)(W2 + n * 256 + k);
        g_W2f[ck * BCH + (Ni * 2 + h) * 64 + g * 8 + tg * 2 + reg] = f2h2(v.x, v.y);
    } else if (blockIdx.x < 384) {
        int idx = (blockIdx.x - 128) * 256 + threadIdx.x;  // 0..65535
        int half = idx >> 15, rem = idx & 32767;
        int reg = rem & 1, tg = (rem >> 1) & 3, g = (rem >> 3) & 7;
        int h = (rem >> 6) & 1, Ni = (rem >> 7) & 31, ck = rem >> 12;
        int n = Ni * 8 + g;
        int k = half * 256 + ck * 32 + h * 16 + reg * 8 + tg * 2;
        float2 v = *(const float2*)(W1 + n * 512 + k);
        g_W1f[half * 8 * BCH + ck * BCH + (Ni * 2 + h) * 64 + g * 8 + tg * 2 + reg] = f2h2(v.x, v.y);
    } else {
        __shared__ int ok;
        if (threadIdx.x == 0) ok = 1;
        __syncthreads();
        int n = E < 1024 ? E : 1024;
        int bad = 0;
        for (int i = threadIdx.x; i < n; i += blockDim.x)
            if (p[2 * i + 1] != 0) bad = 1;
        if (bad) atomicAnd(&ok, 0);
        __syncthreads();
        if (threadIdx.x == 0) g_is64 = ok;
    }
}

// ---------------------------------------------------------------------------
// Kernel 1: g_PQh[i, n0+c] = fp16( sum_k x[i,k] * W1[c, n0+k] )
// CTA 128x256, 16 warps, warp 64x32. Full A (convert+STS) + full B (cp.async,
// 8 groups, progressive wait). (unchanged from R15)
// ---------------------------------------------------------------------------
__global__ __launch_bounds__(512) void node_gemm(const float* __restrict__ x,
                                                 int n_nodes) {
    extern __shared__ unsigned sm[];
    unsigned* Af = sm;               // [EA_WORDS]
    unsigned* Bf = sm + EA_WORDS;    // [8][BCH]

    const int tid = threadIdx.x, lane = tid & 31, warp = tid >> 5;
    const int wm = warp >> 3, wn = warp & 7;
    const int g = lane >> 2, tg = lane & 3;
    const int m0 = blockIdx.x * 128, half = blockIdx.y;

    // ---- issue all B copies (8 groups) before touching A ----
    {
        unsigned bb = (unsigned)__cvta_generic_to_shared(Bf) + tid * 32;
        const unsigned* src = g_W1f + half * 8 * BCH + tid * 8;
#pragma unroll
        for (int ck = 0; ck < 8; ck++) {
            cp16(bb + ck * 16384, src + ck * BCH);
            cp16(bb + ck * 16384 + 16, src + ck * BCH + 4);
            cpcommit();
        }
    }

    // ---- full A load into fragment layout (swizzled) ----
    {
        const int r = tid >> 2, l4 = tid & 3;
        const int Mi = r >> 4, gg = (r & 15) & 7, hi = (r & 15) >> 3;
        const int swz = (gg >> 1) & 3;
        unsigned* fragp = Af + Mi * 16 * AW + gg * 16 + hi;
        int gr = m0 + r; if (gr >= n_nodes) gr = n_nodes - 1;
        const float4* X4 = (const float4*)(x + (long long)gr * D);
#pragma unroll
        for (int i = 0; i < 8; i++) {
            int c8 = i * 4 + l4;           // 8-float group index, 0..31
            float4 a0 = X4[c8 * 2], a1 = X4[c8 * 2 + 1];
            const int Kk = c8 >> 1, hc = (c8 & 1) * 2;
            unsigned* basep = fragp + Kk * AW;
            basep[((0 ^ swz) << 2) + hc] = f2h2(a0.x, a0.y);
            basep[((1 ^ swz) << 2) + hc] = f2h2(a0.z, a0.w);
            basep[((2 ^ swz) << 2) + hc] = f2h2(a1.x, a1.y);
            basep[((3 ^ swz) << 2) + hc] = f2h2(a1.z, a1.w);
        }
    }
    __syncthreads();   // A visible to all warps

    float acc[4][4][4];
#pragma unroll
    for (int a = 0; a < 4; a++)
#pragma unroll
        for (int b = 0; b < 4; b++)
#pragma unroll
            for (int c = 0; c < 4; c++) acc[a][b][c] = 0.f;

    const unsigned aoff = a_rd_off(lane);
    const unsigned* Awarp = Af + (wm * 4) * 16 * AW + aoff;
    for (int kt = 0; kt < 8; ++kt) {
        cpwait(7 - kt);
        __syncthreads();               // chunk kt visible to all threads
        const unsigned* Bc = Bf + kt * BCH;
#pragma unroll
        for (int h = 0; h < 2; ++h) {
            const int Kkg = kt * 2 + h;
            uint4 af[4]; uint2 bf[4];
#pragma unroll
            for (int mi = 0; mi < 4; ++mi)
                af[mi] = *(const uint4*)(Awarp + (mi * 16 + Kkg) * AW);
#pragma unroll
            for (int ni = 0; ni < 4; ++ni)
                bf[ni] = *(const uint2*)(Bc + ((wn * 4 + ni) * 2 + h) * 64 + lane * 2);
#pragma unroll
            for (int mi = 0; mi < 4; ++mi)
#pragma unroll
                for (int ni = 0; ni < 4; ++ni)
                    mma16(acc[mi][ni], (const unsigned*)&af[mi], (const unsigned*)&bf[ni]);
        }
    }

#pragma unroll
    for (int mi = 0; mi < 4; ++mi) {
        int r0 = m0 + wm * 64 + mi * 16 + g;
        int r1 = r0 + 8;
#pragma unroll
        for (int ni = 0; ni < 4; ++ni) {
            int c = half * 256 + wn * 32 + ni * 8 + tg * 2;
            if (r0 < n_nodes)
                *(unsigned*)(g_PQh + (long long)r0 * 512 + c) = f2h2(acc[mi][ni][0], acc[mi][ni][1]);
            if (r1 < n_nodes)
                *(unsigned*)(g_PQh + (long long)r1 * 512 + c) = f2h2(acc[mi][ni][2], acc[mi][ni][3]);
        }
    }
}

// ---------------------------------------------------------------------------
// Kernel 3: 256 edges/CTA as TWO 128-edge M-halves vs one resident W2 image.
// 512 threads, 16 warps, warp 64x32. Gather 8 thr/row (128B-coalesced).
// Half 0: progressive cp.async waits; half 1: wait/barrier-free mainloop.
// ---------------------------------------------------------------------------
__global__ __launch_bounds__(512) void edge_mlp(const void* __restrict__ srcv,
                                                const void* __restrict__ dstv,
                                                const float* __restrict__ b1,
                                                const float* __restrict__ b2,
                                                const float* __restrict__ W3,
                                                const float* __restrict__ b3,
                                                float* __restrict__ out, int E) {
    extern __shared__ unsigned sm[];
    unsigned* Af = sm;                      // [EA_WORDS]
    unsigned* Bf = sm + EA_WORDS;           // [8][BCH]
    float* b2s   = (float*)(Bf + 8 * BCH);  // 256
    float* w3s   = b2s + 256;               // 256
    float* b1s   = w3s + 256;               // 256
    float* score = b1s + 256;               // 128

    const int tid = threadIdx.x, lane = tid & 31, warp = tid >> 5;
    const int wm = warp >> 3, wn = warp & 7;
    const int g = lane >> 2, tg = lane & 3;
    const int e00 = blockIdx.x * 256;
    const int is64 = g_is64;

    // ---- issue all B copies (8 groups) first: they land during the gather ----
    {
        unsigned bb = (unsigned)__cvta_generic_to_shared(Bf) + tid * 32;
        const unsigned* src = g_W2f + tid * 8;
#pragma unroll
        for (int ck = 0; ck < 8; ck++) {
            cp16(bb + ck * 16384, src + ck * BCH);
            cp16(bb + ck * 16384 + 16, src + ck * BCH + 4);
            cpcommit();
        }
    }

    if (tid < 256) {
        b2s[tid] = b2[tid];
        w3s[tid] = W3[tid];
        b1s[tid] = b1[tid];
    }
    const float b3v = b3[0];

    const unsigned aoff = a_rd_off(lane);
    const unsigned* Awarp = Af + (wm * 4) * 16 * AW + aoff;
    const int rbase = tid >> 3, l8 = tid & 7;

#pragma unroll 1
    for (int half = 0; half < 2; ++half) {
        const int e0 = e00 + half * 128;
        if (tid < 128) score[tid] = b3v;
        if (half == 0) __syncthreads();   // b1s (and score) visible before gather use

        // ---- gather + layer 1: 8 threads/row, 2 passes of 64 rows ----
#pragma unroll
        for (int pass = 0; pass < 2; ++pass) {
            const int r = rbase + pass * 64;
            const int Mi = r >> 4, gg = (r & 15) & 7, hi = (r & 15) >> 3;
            const int swz = (gg >> 1) & 3;
            unsigned* fragp = Af + Mi * 16 * AW + gg * 16 + hi;
            int e = e0 + r;
            if (e >= E) e = 0;   // garbage rows computed, never stored
            long long s, d;
            if (is64) { s = ((const long long*)srcv)[e]; d = ((const long long*)dstv)[e]; }
            else      { s = ((const int*)srcv)[e];       d = ((const int*)dstv)[e]; }
            const uint4* P8 = (const uint4*)(g_PQh + s * 512);
            const uint4* Q8 = (const uint4*)(g_PQh + d * 512 + 256);
#pragma unroll
            for (int i = 0; i < 4; i++) {
                int c8 = i * 8 + l8;           // uint4 (8-half) index, 0..31
                uint4 pu = P8[c8], qu = Q8[c8];
                const float* bb = b1s + c8 * 8;
                float v[8];
                float2 a, b;
                a = h2f(pu.x); b = h2f(qu.x);
                v[0] = fmaxf(a.x + b.x + bb[0], 0.f); v[1] = fmaxf(a.y + b.y + bb[1], 0.f);
                a = h2f(pu.y); b = h2f(qu.y);
                v[2] = fmaxf(a.x + b.x + bb[2], 0.f); v[3] = fmaxf(a.y + b.y + bb[3], 0.f);
                a = h2f(pu.z); b = h2f(qu.z);
                v[4] = fmaxf(a.x + b.x + bb[4], 0.f); v[5] = fmaxf(a.y + b.y + bb[5], 0.f);
                a = h2f(pu.w); b = h2f(qu.w);
                v[6] = fmaxf(a.x + b.x + bb[6], 0.f); v[7] = fmaxf(a.y + b.y + bb[7], 0.f);
                const int Kk = c8 >> 1, hc = (c8 & 1) * 2;
                unsigned* basep = fragp + Kk * AW;
#pragma unroll
                for (int t = 0; t < 4; t++)
                    basep[((t ^ swz) << 2) + hc] = f2h2(v[2 * t], v[2 * t + 1]);
            }
        }
        __syncthreads();   // A (and score init) visible

        float acc[4][4][4];
#pragma unroll
        for (int a = 0; a < 4; a++)
#pragma unroll
            for (int b = 0; b < 4; b++)
#pragma unroll
                for (int c = 0; c < 4; c++) acc[a][b][c] = 0.f;

        for (int kt = 0; kt < 8; ++kt) {
            if (half == 0) {
                cpwait(7 - kt);
                __syncthreads();       // chunk kt visible to all threads
            }
            const unsigned* Bc = Bf + kt * BCH;
#pragma unroll
            for (int h = 0; h < 2; ++h) {
                const int Kkg = kt * 2 + h;
                uint4 af[4]; uint2 bf[4];
#pragma unroll
                for (int mi = 0; mi < 4; ++mi)
                    af[mi] = *(const uint4*)(Awarp + (mi * 16 + Kkg) * AW);
#pragma unroll
                for (int ni = 0; ni < 4; ++ni)
                    bf[ni] = *(const uint2*)(Bc + ((wn * 4 + ni) * 2 + h) * 64 + lane * 2);
#pragma unroll
                for (int mi = 0; mi < 4; ++mi)
#pragma unroll
                    for (int ni = 0; ni < 4; ++ni)
                        mma16(acc[mi][ni], (const unsigned*)&af[mi], (const unsigned*)&bf[ni]);
            }
        }

        // ---- fused layer-2 bias/relu + layer-3 dot reduction ----
#pragma unroll
        for (int mi = 0; mi < 4; ++mi) {
            float rs0 = 0.f, rs1 = 0.f;
#pragma unroll
            for (int ni = 0; ni < 4; ++ni) {
                int n = wn * 32 + ni * 8 + tg * 2;
                float w0 = w3s[n], w1 = w3s[n + 1];
                float c0 = b2s[n], c1 = b2s[n + 1];
                rs0 += fmaxf(acc[mi][ni][0] + c0, 0.f) * w0 + fmaxf(acc[mi][ni][1] + c1, 0.f) * w1;
                rs1 += fmaxf(acc[mi][ni][2] + c0, 0.f) * w0 + fmaxf(acc[mi][ni][3] + c1, 0.f) * w1;
            }
            rs0 += __shfl_xor_sync(0xffffffffu, rs0, 1);
            rs0 += __shfl_xor_sync(0xffffffffu, rs0, 2);
            rs1 += __shfl_xor_sync(0xffffffffu, rs1, 1);
            rs1 += __shfl_xor_sync(0xffffffffu, rs1, 2);
            if (tg == 0) {
                atomicAdd(&score[wm * 64 + mi * 16 + g], rs0);
                atomicAdd(&score[wm * 64 + mi * 16 + g + 8], rs1);
            }
        }
        __syncthreads();   // all atomics done before out-write

        if (tid < 128) {
            int e = e0 + tid;
            if (e < E) out[e] = score[tid];
        }
        __syncthreads();   // out-write done before next half reuses score/Af
    }
}

// ---------------------------------------------------------------------------
// Launch
// ---------------------------------------------------------------------------
extern "C" void kernel_launch(void* const* d_in, const int* in_sizes, int n_in,
                              void* d_out, int out_size) {
    const float* x  = (const float*)d_in[0];
    const void*  sv = d_in[1];
    const void*  dv = d_in[2];
    const float* W1 = (const float*)d_in[3];
    const float* b1 = (const float*)d_in[4];
    const float* W2 = (const float*)d_in[5];
    const float* b2 = (const float*)d_in[6];
    const float* W3 = (const float*)d_in[7];
    const float* b3 = (const float*)d_in[8];
    float* out = (float*)d_out;

    const int n_nodes = in_sizes[0] / D;
    const int E       = in_sizes[1];

    const int SM_NODE = (EA_WORDS + 8 * BCH) * 4;          // 198656 B
    const int SM_EDGE = (EA_WORDS + 8 * BCH + 896) * 4;    // 202240 B
    cudaFuncSetAttribute(node_gemm, cudaFuncAttributeMaxDynamicSharedMemorySize, SM_NODE);
    cudaFuncSetAttribute(edge_mlp,  cudaFuncAttributeMaxDynamicSharedMemorySize, SM_EDGE);

    prep<<<385, 256>>>(W1, W2, (const int*)sv, E);

    dim3 g1((n_nodes + 127) / 128, 2);
    node_gemm<<<g1, 512, SM_NODE>>>(x, n_nodes);

    int g2 = (E + 255) / 256;
    edge_mlp<<<g2, 512, SM_EDGE>>>(sv, dv, b1, b2, W3, b3, out, E);
}